// round 1
// baseline (speedup 1.0000x reference)
#include <cuda_runtime.h>
#include <math.h>

#define BATCH 4
#define LSEQ 2048
#define DMODEL 1024
#define NHEADS 8
#define DHEAD 128
#define MROWS (BATCH*LSEQ)

// ---------------- scratch (static device globals; no runtime allocation) ----
__device__ float g_Q [BATCH*NHEADS*LSEQ*DHEAD];
__device__ float g_K [BATCH*NHEADS*LSEQ*DHEAD];
__device__ float g_V [BATCH*NHEADS*LSEQ*DHEAD];
__device__ float g_Y [BATCH*NHEADS*LSEQ*DHEAD];
__device__ float g_Yn[MROWS*DMODEL];
__device__ float g_Sx[MROWS*DMODEL];
__device__ float g_qc[LSEQ*64];
__device__ float g_qs[LSEQ*64];
__device__ float g_kc[LSEQ*64];
__device__ float g_ks[LSEQ*64];
__device__ float g_gpow[NHEADS*LSEQ];

// ---------------- table init -----------------------------------------------
__global__ void init_tables_kernel() {
    int idx = blockIdx.x*blockDim.x + threadIdx.x;
    if (idx < LSEQ*64) {
        int l = idx >> 6, j = idx & 63;
        float dh = (float)DHEAD;
        float base = (2.f*(float)j + 0.4f*dh) / (1.4f*dh);
        float scale = powf(base, (float)l / 512.0f);
        float inv_freq = powf(10000.0f, -(float)j / 64.0f);
        float arg = (float)l * inv_freq;
        float sv = sinf(arg), cv = cosf(arg);
        g_qc[idx] = cv * scale;
        g_qs[idx] = sv * scale;
        float iscale = 1.0f / scale;
        g_kc[idx] = cv * iscale;
        g_ks[idx] = sv * iscale;
    }
    if (idx < NHEADS*LSEQ) {
        int h = idx >> 11, k = idx & (LSEQ-1);
        float lg0 = logf(1.0f/32.0f), lg1 = logf(1.0f/512.0f);
        float lg = lg0 + (lg1 - lg0) * ((float)h / (float)(NHEADS-1));
        float gamma = 1.0f - expf(lg);
        g_gpow[idx] = expf((float)k * logf(gamma));
    }
}

// ---------------- generic 128x128 fp32 GEMM with fused epilogues ------------
// mode 0: C = X @ [W_Q|W_K|W_V]  (N=3072), rotary on Q/K, write [b,h,l,e]
// mode 1: C = X @ W_G            (N=1024), Sx = silu(C) * Yn
// mode 2: C = Sx @ W_O           (N=1024), write d_out
__global__ __launch_bounds__(256) void gemm_kernel(
    const float* __restrict__ A,
    const float* __restrict__ W0, const float* __restrict__ W1, const float* __restrict__ W2,
    float* __restrict__ Cout, int mode)
{
    __shared__ float As[128*16];
    __shared__ float Bs[16*128];
    int tid = threadIdx.x;
    int tx = tid & 15, ty = tid >> 4;
    int rb = blockIdx.y << 7;
    int cb = blockIdx.x << 7;

    const float* Wp; int ldb; int sel = 0, hh = 0;
    if (mode == 0) {
        sel = cb >> 10;                 // 0=Q, 1=K, 2=V
        hh  = (cb & 1023) >> 7;         // head
        const float* Wsel = (sel == 0) ? W0 : (sel == 1) ? W1 : W2;
        Wp = Wsel + (size_t)hh * DMODEL * DHEAD;
        ldb = DHEAD;
    } else {
        Wp = W0 + cb;
        ldb = DMODEL;
    }
    const float* Ap = (mode == 2) ? g_Sx : A;

    float acc[8][8];
    #pragma unroll
    for (int i = 0; i < 8; i++)
        #pragma unroll
        for (int j = 0; j < 8; j++) acc[i][j] = 0.0f;

    for (int kt = 0; kt < DMODEL; kt += 16) {
        #pragma unroll
        for (int i = 0; i < 2; i++) {
            int t = tid + (i << 8);
            int r = t >> 2, k4 = (t & 3) << 2;
            float4 v = *(const float4*)(Ap + (size_t)(rb + r)*DMODEL + kt + k4);
            *(float4*)(As + r*16 + k4) = v;
        }
        #pragma unroll
        for (int i = 0; i < 2; i++) {
            int t = tid + (i << 8);
            int kk = t >> 5, c4 = (t & 31) << 2;
            float4 v = *(const float4*)(Wp + (size_t)(kt + kk)*ldb + c4);
            *(float4*)(Bs + kk*128 + c4) = v;
        }
        __syncthreads();
        #pragma unroll
        for (int kk = 0; kk < 16; kk++) {
            float a[8], b[8];
            #pragma unroll
            for (int i = 0; i < 8; i++) a[i] = As[(ty*8 + i)*16 + kk];
            #pragma unroll
            for (int j = 0; j < 8; j++) b[j] = Bs[kk*128 + tx*8 + j];
            #pragma unroll
            for (int i = 0; i < 8; i++)
                #pragma unroll
                for (int j = 0; j < 8; j++)
                    acc[i][j] = fmaf(a[i], b[j], acc[i][j]);
        }
        __syncthreads();
    }

    int c0 = tx << 3;
    if (mode == 0) {
        #pragma unroll
        for (int i = 0; i < 8; i++) {
            int r  = rb + ty*8 + i;
            int bb = r >> 11;
            int l  = r & (LSEQ - 1);
            size_t dstoff = ((size_t)(bb*NHEADS + hh)*LSEQ + l)*DHEAD + c0;
            if (sel == 2) {
                *(float4*)(g_V + dstoff)     = make_float4(acc[i][0], acc[i][1], acc[i][2], acc[i][3]);
                *(float4*)(g_V + dstoff + 4) = make_float4(acc[i][4], acc[i][5], acc[i][6], acc[i][7]);
            } else {
                const float* ct = (sel == 0) ? g_qc : g_kc;
                const float* st = (sel == 0) ? g_qs : g_ks;
                float o[8];
                #pragma unroll
                for (int p = 0; p < 4; p++) {
                    int jj = (c0 >> 1) + p;
                    float cv = ct[l*64 + jj], sv = st[l*64 + jj];
                    float x1 = acc[i][2*p], x2 = acc[i][2*p + 1];
                    o[2*p]     = x1*cv - x2*sv;
                    o[2*p + 1] = x2*cv + x1*sv;
                }
                float* dst = ((sel == 0) ? g_Q : g_K) + dstoff;
                *(float4*)(dst)     = make_float4(o[0], o[1], o[2], o[3]);
                *(float4*)(dst + 4) = make_float4(o[4], o[5], o[6], o[7]);
            }
        }
    } else if (mode == 1) {
        #pragma unroll
        for (int i = 0; i < 8; i++) {
            int r = rb + ty*8 + i;
            size_t off = (size_t)r*DMODEL + cb + c0;
            #pragma unroll
            for (int j = 0; j < 8; j++) {
                float g  = acc[i][j];
                float sg = g / (1.0f + expf(-g));   // g * sigmoid(g)
                g_Sx[off + j] = sg * g_Yn[off + j];
            }
        }
    } else {
        #pragma unroll
        for (int i = 0; i < 8; i++) {
            int r = rb + ty*8 + i;
            size_t off = (size_t)r*DMODEL + cb + c0;
            *(float4*)(Cout + off)     = make_float4(acc[i][0], acc[i][1], acc[i][2], acc[i][3]);
            *(float4*)(Cout + off + 4) = make_float4(acc[i][4], acc[i][5], acc[i][6], acc[i][7]);
        }
    }
}

// ---------------- retention attention: Y = (Q K^T ∘ D) V --------------------
// grid: (16 n-tiles [reversed for balance], NHEADS, BATCH); 256 threads
// smem: Q[128][128] | K^T[128][65] | V[64][128] | S[128][65]
#define ATT_SMEM_FLOATS (128*128 + 128*65 + 64*128 + 128*65)
#define ATT_SMEM_BYTES  (ATT_SMEM_FLOATS * 4)

__global__ __launch_bounds__(256) void attn_kernel() {
    extern __shared__ float sm[];
    float* Qs = sm;                  // [n][e]  128x128
    float* Ks = Qs + 128*128;        // [e][m]  128x(64 pad 65)
    float* Vs = Ks + 128*65;         // [m][v]  64x128
    float* Ss = Vs + 64*128;         // [n][m]  128x(64 pad 65)

    int nt = (int)(gridDim.x - 1) - (int)blockIdx.x;   // big tiles first
    int h  = blockIdx.y, bb = blockIdx.z;
    int tid = threadIdx.x;
    int tx = tid & 15, ty = tid >> 4;
    size_t hb = ((size_t)(bb*NHEADS + h)) * LSEQ * DHEAD;
    const float* Qg = g_Q + hb;
    const float* Kg = g_K + hb;
    const float* Vg = g_V + hb;
    float* Yg = g_Y + hb;
    const float* gp = g_gpow + h*LSEQ;
    int nb = nt << 7;

    for (int t = tid; t < (128*128)/4; t += 256)
        ((float4*)Qs)[t] = *(const float4*)(Qg + (size_t)nb*DHEAD + t*4);

    int n0 = ty << 3, m0 = tx << 2, v0 = tx << 3;
    float accY[8][8];
    #pragma unroll
    for (int i = 0; i < 8; i++)
        #pragma unroll
        for (int j = 0; j < 8; j++) accY[i][j] = 0.0f;

    int nMt = 2*nt + 2;
    for (int mt = 0; mt < nMt; mt++) {
        int mb = mt << 6;
        __syncthreads();
        // load K (transposed) and V tiles
        for (int t = tid; t < (64*128)/4; t += 256) {
            int m = t >> 5, e4 = (t & 31) << 2;
            float4 kv = *(const float4*)(Kg + (size_t)(mb + m)*DHEAD + e4);
            Ks[(e4 + 0)*65 + m] = kv.x;
            Ks[(e4 + 1)*65 + m] = kv.y;
            Ks[(e4 + 2)*65 + m] = kv.z;
            Ks[(e4 + 3)*65 + m] = kv.w;
            *(float4*)(Vs + m*128 + e4) = *(const float4*)(Vg + (size_t)(mb + m)*DHEAD + e4);
        }
        __syncthreads();

        // S[128][64] = Q K^T ; each thread: 8 rows x 4 cols
        float sacc[8][4];
        #pragma unroll
        for (int i = 0; i < 8; i++)
            #pragma unroll
            for (int j = 0; j < 4; j++) sacc[i][j] = 0.0f;
        #pragma unroll 8
        for (int e = 0; e < 128; e++) {
            float a[8], b[4];
            #pragma unroll
            for (int i = 0; i < 8; i++) a[i] = Qs[(n0 + i)*128 + e];
            #pragma unroll
            for (int j = 0; j < 4; j++) b[j] = Ks[e*65 + m0 + j];
            #pragma unroll
            for (int i = 0; i < 8; i++)
                #pragma unroll
                for (int j = 0; j < 4; j++)
                    sacc[i][j] = fmaf(a[i], b[j], sacc[i][j]);
        }
        // decay mask + store to smem
        #pragma unroll
        for (int i = 0; i < 8; i++) {
            int ng = nb + n0 + i;
            #pragma unroll
            for (int j = 0; j < 4; j++) {
                int d = ng - (mb + m0 + j);
                Ss[(n0 + i)*65 + m0 + j] = (d >= 0) ? sacc[i][j]*gp[d] : 0.0f;
            }
        }
        __syncthreads();

        // Y += S @ V ; each thread: 8 rows x 8 v-cols
        #pragma unroll 4
        for (int m = 0; m < 64; m++) {
            float sv[8];
            #pragma unroll
            for (int i = 0; i < 8; i++) sv[i] = Ss[(n0 + i)*65 + m];
            float4 va = *(const float4*)(Vs + m*128 + v0);
            float4 vb = *(const float4*)(Vs + m*128 + v0 + 4);
            float vv[8] = {va.x, va.y, va.z, va.w, vb.x, vb.y, vb.z, vb.w};
            #pragma unroll
            for (int i = 0; i < 8; i++)
                #pragma unroll
                for (int j = 0; j < 8; j++)
                    accY[i][j] = fmaf(sv[i], vv[j], accY[i][j]);
        }
    }

    #pragma unroll
    for (int i = 0; i < 8; i++) {
        size_t off = (size_t)(nb + n0 + i)*DHEAD + v0;
        *(float4*)(Yg + off)     = make_float4(accY[i][0], accY[i][1], accY[i][2], accY[i][3]);
        *(float4*)(Yg + off + 4) = make_float4(accY[i][4], accY[i][5], accY[i][6], accY[i][7]);
    }
}

// ---------------- group norm over head dim (128), transpose to [b,l,d] ------
__global__ __launch_bounds__(256) void groupnorm_kernel(
    const float* __restrict__ gw, const float* __restrict__ gb)
{
    int gtid = blockIdx.x*blockDim.x + threadIdx.x;
    int warp = gtid >> 5;
    int lane = gtid & 31;
    if (warp >= BATCH*NHEADS*LSEQ) return;
    const float* y = g_Y + (size_t)warp * DHEAD;
    float4 v = ((const float4*)y)[lane];
    float s  = v.x + v.y + v.z + v.w;
    float ss = v.x*v.x + v.y*v.y + v.z*v.z + v.w*v.w;
    #pragma unroll
    for (int o = 16; o > 0; o >>= 1) {
        s  += __shfl_xor_sync(0xffffffffu, s,  o);
        ss += __shfl_xor_sync(0xffffffffu, ss, o);
    }
    float mean = s * (1.0f/DHEAD);
    float var  = ss * (1.0f/DHEAD) - mean*mean;
    float rstd = rsqrtf(var + 1e-5f);
    int l  = warp & (LSEQ - 1);
    int h  = (warp >> 11) & (NHEADS - 1);
    int bb = warp >> 14;
    int dcol = h*DHEAD + (lane << 2);
    float4 w4 = *(const float4*)(gw + dcol);
    float4 b4 = *(const float4*)(gb + dcol);
    float4 o;
    o.x = (v.x - mean)*rstd*w4.x + b4.x;
    o.y = (v.y - mean)*rstd*w4.y + b4.y;
    o.z = (v.z - mean)*rstd*w4.z + b4.z;
    o.w = (v.w - mean)*rstd*w4.w + b4.w;
    *(float4*)(g_Yn + (size_t)(bb*LSEQ + l)*DMODEL + dcol) = o;
}

// ---------------- launch ----------------------------------------------------
extern "C" void kernel_launch(void* const* d_in, const int* in_sizes, int n_in,
                              void* d_out, int out_size) {
    const float* X  = (const float*)d_in[0];
    const float* WQ = (const float*)d_in[1];
    const float* WK = (const float*)d_in[2];
    const float* WV = (const float*)d_in[3];
    const float* WG = (const float*)d_in[4];
    const float* WO = (const float*)d_in[5];
    const float* gw = (const float*)d_in[6];
    const float* gb = (const float*)d_in[7];
    float* out = (float*)d_out;

    cudaFuncSetAttribute(attn_kernel, cudaFuncAttributeMaxDynamicSharedMemorySize, ATT_SMEM_BYTES);

    init_tables_kernel<<<512, 256>>>();

    // QKV projection + rotary (N = 3072)
    gemm_kernel<<<dim3(24, 64), 256>>>(X, WQ, WK, WV, nullptr, 0);

    // retention attention
    attn_kernel<<<dim3(16, NHEADS, BATCH), 256, ATT_SMEM_BYTES>>>();

    // group norm + transpose
    groupnorm_kernel<<<(BATCH*NHEADS*LSEQ*32)/256, 256>>>(gw, gb);

    // gate GEMM + silu * Yn
    gemm_kernel<<<dim3(8, 64), 256>>>(X, WG, nullptr, nullptr, nullptr, 1);

    // output GEMM
    gemm_kernel<<<dim3(8, 64), 256>>>(nullptr, WO, nullptr, nullptr, out, 2);
}

// round 3
// speedup vs baseline: 3.6089x; 3.6089x over previous
#include <cuda_runtime.h>
#include <math.h>
#include <stdint.h>

#define BATCH 4
#define LSEQ 2048
#define DMODEL 1024
#define NHEADS 8
#define DHEAD 128
#define MROWS (BATCH*LSEQ)

// ---------------- device scratch --------------------------------------------
__device__ float g_Wt[5120*1024];                 // transposed+rounded weights [n][k]
__device__ float g_Xr[MROWS*DMODEL];              // tf32-rounded X
__device__ float g_Q [BATCH*NHEADS*LSEQ*DHEAD];   // [b,h,l,e] rounded
__device__ float g_K [BATCH*NHEADS*LSEQ*DHEAD];
__device__ float g_Vt[BATCH*NHEADS*DHEAD*LSEQ];   // [b,h,v,l] rounded
__device__ float g_Y [BATCH*NHEADS*LSEQ*DHEAD];
__device__ float g_Yn[MROWS*DMODEL];
__device__ float g_Sx[MROWS*DMODEL];              // silu(G)*Yn rounded
__device__ float g_qc[LSEQ*64];
__device__ float g_qs[LSEQ*64];
__device__ float g_kc[LSEQ*64];
__device__ float g_ks[LSEQ*64];
__device__ float g_gpow[NHEADS*LSEQ];

// ---------------- helpers ----------------------------------------------------
__device__ __forceinline__ uint32_t smem_u32(const void* p) {
    uint32_t a;
    asm("{ .reg .u64 t; cvta.to.shared.u64 t, %1; cvt.u32.u64 %0, t; }" : "=r"(a) : "l"(p));
    return a;
}
__device__ __forceinline__ float rna_tf32(float x) {
    uint32_t u; asm("cvt.rna.tf32.f32 %0, %1;" : "=r"(u) : "f"(x)); return __uint_as_float(u);
}
__device__ __forceinline__ void mma8(float d[4], const uint32_t a[4], uint32_t b0, uint32_t b1) {
    asm volatile(
        "mma.sync.aligned.m16n8k8.row.col.f32.tf32.tf32.f32 "
        "{%0,%1,%2,%3}, {%4,%5,%6,%7}, {%8,%9}, {%0,%1,%2,%3};"
        : "+f"(d[0]), "+f"(d[1]), "+f"(d[2]), "+f"(d[3])
        : "r"(a[0]), "r"(a[1]), "r"(a[2]), "r"(a[3]), "r"(b0), "r"(b1));
}
#define CP16(dst, src)  asm volatile("cp.async.cg.shared.global [%0], [%1], 16;" :: "r"(dst), "l"(src) : "memory")
#define CPCOMMIT()      asm volatile("cp.async.commit_group;" ::: "memory")
#define CPWAIT0()       asm volatile("cp.async.wait_group 0;" ::: "memory")
#define CPWAIT1()       asm volatile("cp.async.wait_group 1;" ::: "memory")

// ---------------- table init -------------------------------------------------
__global__ void init_tables_kernel() {
    int idx = blockIdx.x*blockDim.x + threadIdx.x;
    if (idx < LSEQ*64) {
        int l = idx >> 6, j = idx & 63;
        float dh = (float)DHEAD;
        float base = (2.f*(float)j + 0.4f*dh) / (1.4f*dh);
        float scale = powf(base, (float)l / 512.0f);
        float inv_freq = powf(10000.0f, -(float)j / 64.0f);
        float arg = (float)l * inv_freq;
        float sv = sinf(arg), cv = cosf(arg);
        g_qc[idx] = cv * scale;
        g_qs[idx] = sv * scale;
        float iscale = 1.0f / scale;
        g_kc[idx] = cv * iscale;
        g_ks[idx] = sv * iscale;
    }
    if (idx < NHEADS*LSEQ) {
        int h = idx >> 11, k = idx & (LSEQ-1);
        float lg0 = logf(1.0f/32.0f), lg1 = logf(1.0f/512.0f);
        float lg = lg0 + (lg1 - lg0) * ((float)h / (float)(NHEADS-1));
        float gamma = 1.0f - expf(lg);
        g_gpow[idx] = expf((float)k * logf(gamma));
    }
}

// ---------------- round X to tf32 -------------------------------------------
__global__ void roundx_kernel(const float* __restrict__ X) {
    int idx = blockIdx.x*blockDim.x + threadIdx.x;
    float4 v = ((const float4*)X)[idx];
    v.x = rna_tf32(v.x); v.y = rna_tf32(v.y); v.z = rna_tf32(v.z); v.w = rna_tf32(v.w);
    ((float4*)g_Xr)[idx] = v;
}

// ---------------- weight transpose + round ----------------------------------
// g_Wt[n][k], n: [0,3072)=QKV heads, [3072,4096)=WG cols, [4096,5120)=WO cols
__global__ void wtrans_kernel(const float* __restrict__ WQ, const float* __restrict__ WK,
                              const float* __restrict__ WV, const float* __restrict__ WG,
                              const float* __restrict__ WO) {
    __shared__ float t[32][33];
    int kT = blockIdx.x << 5, nT = blockIdx.y << 5;
    int tx = threadIdx.x, ty = threadIdx.y;   // 32 x 8
    #pragma unroll
    for (int r = 0; r < 4; r++) {
        int n = nT + tx, k = kT + ty + 8*r;
        float v;
        if (n < 3072) {
            int sel = n >> 10, h = (n >> 7) & 7, e = n & 127;
            const float* W = (sel == 0) ? WQ : (sel == 1) ? WK : WV;
            v = W[(size_t)h*131072 + (size_t)k*128 + e];
        } else if (n < 4096) {
            v = WG[(size_t)k*1024 + (n - 3072)];
        } else {
            v = WO[(size_t)k*1024 + (n - 4096)];
        }
        t[ty + 8*r][tx] = v;
    }
    __syncthreads();
    #pragma unroll
    for (int r = 0; r < 4; r++) {
        int n = nT + ty + 8*r, k = kT + tx;
        g_Wt[(size_t)n*1024 + k] = rna_tf32(t[tx][ty + 8*r]);
    }
}

// ---------------- unified tf32 mma.sync GEMM --------------------------------
// C[128x128] = A[128x1024] x Wt_rows[128][1024]^T  (contract over k)
// mode 0: A=g_Xr, QKV -> rotary -> g_Q/g_K ; V -> g_Vt transposed
// mode 1: A=g_Xr, WG -> g_Sx = silu(C)*g_Yn (rounded)
// mode 2: A=g_Sx, WO -> Cout
#define MM_SMEM (18432*4)
__global__ __launch_bounds__(256) void mm_kernel(float* __restrict__ Cout, int mode, int wRowOff) {
    extern __shared__ float sm[];
    const int tid = threadIdx.x;
    const int wid = tid >> 5, lane = tid & 31;
    const int q = lane >> 2, tq = lane & 3;
    const int wm = wid & 3, wn = wid >> 2;
    const int rb = blockIdx.y << 7, cb = blockIdx.x << 7;

    const float* Ap = ((mode == 2) ? g_Sx : g_Xr) + (size_t)rb * 1024;
    const float* Bp = g_Wt + (size_t)(wRowOff + cb) * 1024;

    float* Asm[2] = { sm, sm + 4608 };
    float* Bsm[2] = { sm + 9216, sm + 13824 };
    uint32_t smb = smem_u32(sm);
    uint32_t asb[2] = { smb, smb + 4608u*4u };
    uint32_t bsb[2] = { smb + 9216u*4u, smb + 13824u*4u };

    float acc[2][8][4];
    #pragma unroll
    for (int mi = 0; mi < 2; mi++)
        #pragma unroll
        for (int ni = 0; ni < 8; ni++)
            #pragma unroll
            for (int c = 0; c < 4; c++) acc[mi][ni][c] = 0.0f;

    // prologue: stage k-chunk 0 into buf 0
    #pragma unroll
    for (int i = 0; i < 4; i++) {
        int idx = tid + (i << 8);
        int r = idx >> 3, c4 = (idx & 7) << 2;
        CP16(asb[0] + (uint32_t)(r*36 + c4)*4u, Ap + (size_t)r*1024 + c4);
        CP16(bsb[0] + (uint32_t)(r*36 + c4)*4u, Bp + (size_t)r*1024 + c4);
    }
    CPCOMMIT();

    #pragma unroll 1
    for (int k = 0; k < 32; k++) {
        int buf = k & 1;
        if (k + 1 < 32) {
            int kt = (k + 1) * 32, nb_ = buf ^ 1;
            #pragma unroll
            for (int i = 0; i < 4; i++) {
                int idx = tid + (i << 8);
                int r = idx >> 3, c4 = (idx & 7) << 2;
                CP16(asb[nb_] + (uint32_t)(r*36 + c4)*4u, Ap + (size_t)r*1024 + kt + c4);
                CP16(bsb[nb_] + (uint32_t)(r*36 + c4)*4u, Bp + (size_t)r*1024 + kt + c4);
            }
            CPCOMMIT();
            CPWAIT1();
        } else {
            CPWAIT0();
        }
        __syncthreads();
        const float* A_ = Asm[buf];
        const float* B_ = Bsm[buf];
        #pragma unroll
        for (int ks = 0; ks < 4; ks++) {
            int c = ks*8 + tq;
            uint32_t af[2][4];
            #pragma unroll
            for (int mi = 0; mi < 2; mi++) {
                int r = wm*32 + mi*16 + q;
                af[mi][0] = __float_as_uint(A_[r*36 + c]);
                af[mi][1] = __float_as_uint(A_[(r+8)*36 + c]);
                af[mi][2] = __float_as_uint(A_[r*36 + c + 4]);
                af[mi][3] = __float_as_uint(A_[(r+8)*36 + c + 4]);
            }
            #pragma unroll
            for (int ni = 0; ni < 8; ni++) {
                int n = wn*64 + ni*8 + q;
                uint32_t b0 = __float_as_uint(B_[n*36 + c]);
                uint32_t b1 = __float_as_uint(B_[n*36 + c + 4]);
                mma8(acc[0][ni], af[0], b0, b1);
                mma8(acc[1][ni], af[1], b0, b1);
            }
        }
        __syncthreads();
    }

    // ---------------- epilogue ----------------
    int sel = 0, hh = 0;
    if (mode == 0) { sel = blockIdx.x >> 3; hh = blockIdx.x & 7; }

    #pragma unroll
    for (int mi = 0; mi < 2; mi++) {
        #pragma unroll
        for (int half = 0; half < 2; half++) {
            int row = rb + wm*32 + mi*16 + q + half*8;
            int bb = row >> 11, l = row & (LSEQ - 1);
            #pragma unroll
            for (int ni = 0; ni < 8; ni++) {
                int colb = wn*64 + ni*8 + 2*tq;
                float x1 = acc[mi][ni][half*2 + 0];
                float x2 = acc[mi][ni][half*2 + 1];
                if (mode == 0) {
                    size_t hbase = (size_t)(bb*NHEADS + hh);
                    if (sel == 2) {
                        float* vt = g_Vt + hbase * (size_t)(DHEAD*LSEQ);
                        vt[(size_t)colb * LSEQ + l]       = rna_tf32(x1);
                        vt[(size_t)(colb + 1) * LSEQ + l] = rna_tf32(x2);
                    } else {
                        const float* ct = (sel == 0) ? g_qc : g_kc;
                        const float* st = (sel == 0) ? g_qs : g_ks;
                        int jj = colb >> 1;
                        float cv = ct[l*64 + jj], sv = st[l*64 + jj];
                        float2 o;
                        o.x = rna_tf32(x1*cv - x2*sv);
                        o.y = rna_tf32(x2*cv + x1*sv);
                        float* dst = ((sel == 0) ? g_Q : g_K) + (hbase*LSEQ + l)*DHEAD + colb;
                        *(float2*)dst = o;
                    }
                } else if (mode == 1) {
                    size_t off = (size_t)row*1024 + cb + colb;
                    float2 yn = *(const float2*)(g_Yn + off);
                    float2 o;
                    o.x = rna_tf32((x1 / (1.0f + expf(-x1))) * yn.x);
                    o.y = rna_tf32((x2 / (1.0f + expf(-x2))) * yn.y);
                    *(float2*)(g_Sx + off) = o;
                } else {
                    size_t off = (size_t)row*1024 + cb + colb;
                    *(float2*)(Cout + off) = make_float2(x1, x2);
                }
            }
        }
    }
}

// ---------------- attention: Y = (Q K^T ∘ D) V via mma.sync -----------------
// smem: Qs[128][132] | Ks[64][132] | Vs[128][68] | Ss[128][68]
#define ATT_SMEM ((16896 + 8448 + 8704 + 8704)*4)
__global__ __launch_bounds__(256) void attn_kernel() {
    extern __shared__ float sm[];
    float* Qs = sm;
    float* Ks = sm + 16896;
    float* Vs = sm + 25344;
    float* Ss = sm + 34048;
    uint32_t smb = smem_u32(sm);
    uint32_t ksb = smb + 16896u*4u;
    uint32_t vsb = smb + 25344u*4u;

    const int tid = threadIdx.x;
    const int wid = tid >> 5, lane = tid & 31;
    const int q = lane >> 2, tq = lane & 3;
    const int wm = wid & 3, wn = wid >> 2;

    int nt = (int)(gridDim.x - 1) - (int)blockIdx.x;   // big tiles first
    int h = blockIdx.y, b = blockIdx.z;
    int nb = nt << 7;

    size_t hb = (size_t)(b*NHEADS + h);
    const float* Qg = g_Q + hb * (size_t)(LSEQ*DHEAD);
    const float* Kg = g_K + hb * (size_t)(LSEQ*DHEAD);
    const float* Vg = g_Vt + hb * (size_t)(DHEAD*LSEQ);
    float* Yg = g_Y + hb * (size_t)(LSEQ*DHEAD);
    const float* gp = g_gpow + h * LSEQ;

    // stage Q tile
    #pragma unroll
    for (int i = 0; i < 16; i++) {
        int idx = tid + (i << 8);
        int r = idx >> 5, c4 = (idx & 31) << 2;
        *(float4*)&Qs[r*132 + c4] = *(const float4*)(Qg + (size_t)(nb + r)*DHEAD + c4);
    }

    float yacc[2][8][4];
    #pragma unroll
    for (int mi = 0; mi < 2; mi++)
        #pragma unroll
        for (int ni = 0; ni < 8; ni++)
            #pragma unroll
            for (int c = 0; c < 4; c++) yacc[mi][ni][c] = 0.0f;

    int nMt = 2*nt + 2;
    #pragma unroll 1
    for (int mt = 0; mt < nMt; mt++) {
        int mb_ = mt << 6;
        __syncthreads();   // prev iter done reading Ks/Vs (and Q staged on iter 0)
        // stage K [64][128] and V [128][64]
        #pragma unroll
        for (int i = 0; i < 8; i++) {
            int idx = tid + (i << 8);
            int r = idx >> 5, c4 = (idx & 31) << 2;
            CP16(ksb + (uint32_t)(r*132 + c4)*4u, Kg + (size_t)(mb_ + r)*DHEAD + c4);
        }
        #pragma unroll
        for (int i = 0; i < 8; i++) {
            int idx = tid + (i << 8);
            int r = idx >> 4, c4 = (idx & 15) << 2;
            CP16(vsb + (uint32_t)(r*68 + c4)*4u, Vg + (size_t)r*LSEQ + mb_ + c4);
        }
        CPCOMMIT(); CPWAIT0();
        __syncthreads();

        // S = Q K^T  (M=128, N=64, K=128)
        float sacc[2][4][4];
        #pragma unroll
        for (int mi = 0; mi < 2; mi++)
            #pragma unroll
            for (int ni = 0; ni < 4; ni++)
                #pragma unroll
                for (int c = 0; c < 4; c++) sacc[mi][ni][c] = 0.0f;
        #pragma unroll
        for (int ks = 0; ks < 16; ks++) {
            int c = ks*8 + tq;
            uint32_t af[2][4];
            #pragma unroll
            for (int mi = 0; mi < 2; mi++) {
                int r = wm*32 + mi*16 + q;
                af[mi][0] = __float_as_uint(Qs[r*132 + c]);
                af[mi][1] = __float_as_uint(Qs[(r+8)*132 + c]);
                af[mi][2] = __float_as_uint(Qs[r*132 + c + 4]);
                af[mi][3] = __float_as_uint(Qs[(r+8)*132 + c + 4]);
            }
            #pragma unroll
            for (int ni = 0; ni < 4; ni++) {
                int m = wn*32 + ni*8 + q;
                uint32_t b0 = __float_as_uint(Ks[m*132 + c]);
                uint32_t b1 = __float_as_uint(Ks[m*132 + c + 4]);
                mma8(sacc[0][ni], af[0], b0, b1);
                mma8(sacc[1][ni], af[1], b0, b1);
            }
        }

        // decay + round + store S to smem
        #pragma unroll
        for (int mi = 0; mi < 2; mi++) {
            #pragma unroll
            for (int half = 0; half < 2; half++) {
                int r = wm*32 + mi*16 + q + half*8;
                int n = nb + r;
                #pragma unroll
                for (int ni = 0; ni < 4; ni++) {
                    int m = wn*32 + ni*8 + 2*tq;
                    int d0 = n - (mb_ + m);
                    int d1 = d0 - 1;
                    float v0 = (d0 >= 0) ? rna_tf32(sacc[mi][ni][half*2+0] * __ldg(gp + d0)) : 0.0f;
                    float v1 = (d1 >= 0) ? rna_tf32(sacc[mi][ni][half*2+1] * __ldg(gp + d1)) : 0.0f;
                    *(float2*)&Ss[r*68 + m] = make_float2(v0, v1);
                }
            }
        }
        __syncthreads();

        // Y += S V^T  (M=128, N=128, K=64)
        #pragma unroll
        for (int ks = 0; ks < 8; ks++) {
            int c = ks*8 + tq;
            uint32_t af[2][4];
            #pragma unroll
            for (int mi = 0; mi < 2; mi++) {
                int r = wm*32 + mi*16 + q;
                af[mi][0] = __float_as_uint(Ss[r*68 + c]);
                af[mi][1] = __float_as_uint(Ss[(r+8)*68 + c]);
                af[mi][2] = __float_as_uint(Ss[r*68 + c + 4]);
                af[mi][3] = __float_as_uint(Ss[(r+8)*68 + c + 4]);
            }
            #pragma unroll
            for (int ni = 0; ni < 8; ni++) {
                int v = wn*64 + ni*8 + q;
                uint32_t b0 = __float_as_uint(Vs[v*68 + c]);
                uint32_t b1 = __float_as_uint(Vs[v*68 + c + 4]);
                mma8(yacc[0][ni], af[0], b0, b1);
                mma8(yacc[1][ni], af[1], b0, b1);
            }
        }
    }

    // write Y
    #pragma unroll
    for (int mi = 0; mi < 2; mi++) {
        #pragma unroll
        for (int half = 0; half < 2; half++) {
            int row = wm*32 + mi*16 + q + half*8;
            #pragma unroll
            for (int ni = 0; ni < 8; ni++) {
                int v = wn*64 + ni*8 + 2*tq;
                *(float2*)(Yg + (size_t)(nb + row)*DHEAD + v) =
                    make_float2(yacc[mi][ni][half*2+0], yacc[mi][ni][half*2+1]);
            }
        }
    }
}

// ---------------- group norm over head dim (128), transpose to [b,l,d] ------
__global__ __launch_bounds__(256) void groupnorm_kernel(
    const float* __restrict__ gw, const float* __restrict__ gb)
{
    int gtid = blockIdx.x*blockDim.x + threadIdx.x;
    int warp = gtid >> 5;
    int lane = gtid & 31;
    if (warp >= BATCH*NHEADS*LSEQ) return;
    const float* y = g_Y + (size_t)warp * DHEAD;
    float4 v = ((const float4*)y)[lane];
    float s  = v.x + v.y + v.z + v.w;
    float ss = v.x*v.x + v.y*v.y + v.z*v.z + v.w*v.w;
    #pragma unroll
    for (int o = 16; o > 0; o >>= 1) {
        s  += __shfl_xor_sync(0xffffffffu, s,  o);
        ss += __shfl_xor_sync(0xffffffffu, ss, o);
    }
    float mean = s * (1.0f/DHEAD);
    float var  = ss * (1.0f/DHEAD) - mean*mean;
    float rstd = rsqrtf(var + 1e-5f);
    int l  = warp & (LSEQ - 1);
    int h  = (warp >> 11) & (NHEADS - 1);
    int bb = warp >> 14;
    int dcol = h*DHEAD + (lane << 2);
    float4 w4 = *(const float4*)(gw + dcol);
    float4 b4 = *(const float4*)(gb + dcol);
    float4 o;
    o.x = (v.x - mean)*rstd*w4.x + b4.x;
    o.y = (v.y - mean)*rstd*w4.y + b4.y;
    o.z = (v.z - mean)*rstd*w4.z + b4.z;
    o.w = (v.w - mean)*rstd*w4.w + b4.w;
    *(float4*)(g_Yn + (size_t)(bb*LSEQ + l)*DMODEL + dcol) = o;
}

// ---------------- launch ----------------------------------------------------
extern "C" void kernel_launch(void* const* d_in, const int* in_sizes, int n_in,
                              void* d_out, int out_size) {
    const float* X  = (const float*)d_in[0];
    const float* WQ = (const float*)d_in[1];
    const float* WK = (const float*)d_in[2];
    const float* WV = (const float*)d_in[3];
    const float* WG = (const float*)d_in[4];
    const float* WO = (const float*)d_in[5];
    const float* gw = (const float*)d_in[6];
    const float* gb = (const float*)d_in[7];
    float* out = (float*)d_out;

    cudaFuncSetAttribute(mm_kernel, cudaFuncAttributeMaxDynamicSharedMemorySize, MM_SMEM);
    cudaFuncSetAttribute(attn_kernel, cudaFuncAttributeMaxDynamicSharedMemorySize, ATT_SMEM);

    init_tables_kernel<<<512, 256>>>();
    roundx_kernel<<<(MROWS*DMODEL/4)/256, 256>>>(X);
    wtrans_kernel<<<dim3(32, 160), dim3(32, 8)>>>(WQ, WK, WV, WG, WO);

    // QKV projection + rotary + V transpose
    mm_kernel<<<dim3(24, 64), 256, MM_SMEM>>>(nullptr, 0, 0);

    // retention attention
    attn_kernel<<<dim3(16, NHEADS, BATCH), 256, ATT_SMEM>>>();

    // group norm + transpose
    groupnorm_kernel<<<(BATCH*NHEADS*LSEQ*32)/256, 256>>>(gw, gb);

    // gate GEMM + silu*Yn
    mm_kernel<<<dim3(8, 64), 256, MM_SMEM>>>(nullptr, 1, 3072);

    // output GEMM
    mm_kernel<<<dim3(8, 64), 256, MM_SMEM>>>(out, 2, 4096);
}